// round 17
// baseline (speedup 1.0000x reference)
#include <cuda_runtime.h>
#include <cuda_fp16.h>
#include <cstdint>

#define EMB   768
#define EMB3  2304
#define NHEAD 12
#define HDIM  64
#define SEQ   1024
#define BATCH 8
#define MROWS (BATCH * SEQ)   // 8192

// Q pre-scale: 0.125 * log2(e)  (folded into Q at GEMM1 epilogue)
#define QSCALE 0.1803368787f

// ---------------------------------------------------------------------------
// Scratch (no cudaMalloc allowed).
// ---------------------------------------------------------------------------
__device__ __align__(256) __half g_x16 [(size_t)MROWS * EMB];       // x fp16
__device__ __align__(256) __half g_wat16[(size_t)EMB3 * EMB];       // W_attn^T [N,K] fp16
__device__ __align__(256) __half g_wpt16[(size_t)EMB * EMB];        // W_proj^T [N,K] fp16
__device__ __align__(256) __half g_qk16[(size_t)MROWS * 2 * EMB];   // Qs|K fp16 [M,1536]
__device__ __align__(256) __half g_vt16[(size_t)BATCH * NHEAD * HDIM * SEQ]; // V^T fp16 [B,H,d,t]
__device__ __align__(256) __half g_at16[(size_t)MROWS * EMB];       // attn out fp16

// ---------------------------------------------------------------------------
// Helpers
// ---------------------------------------------------------------------------
__device__ __forceinline__ void cpa16(void* smem_dst, const void* gmem_src) {
    uint32_t s = (uint32_t)__cvta_generic_to_shared(smem_dst);
    asm volatile("cp.async.cg.shared.global [%0], [%1], 16;\n" :: "r"(s), "l"(gmem_src));
}
__device__ __forceinline__ void cpa_commit() { asm volatile("cp.async.commit_group;\n"); }
template<int N>
__device__ __forceinline__ void cpa_wait() { asm volatile("cp.async.wait_group %0;\n" :: "n"(N) : "memory"); }

__device__ __forceinline__ void mma_f16(float& d0, float& d1, float& d2, float& d3,
                                        uint32_t a0, uint32_t a1, uint32_t a2, uint32_t a3,
                                        uint32_t b0, uint32_t b1) {
    asm volatile(
        "mma.sync.aligned.m16n8k16.row.col.f32.f16.f16.f32 "
        "{%0,%1,%2,%3}, {%4,%5,%6,%7}, {%8,%9}, {%0,%1,%2,%3};\n"
        : "+f"(d0), "+f"(d1), "+f"(d2), "+f"(d3)
        : "r"(a0), "r"(a1), "r"(a2), "r"(a3), "r"(b0), "r"(b1));
}

__device__ __forceinline__ void ldsm4(uint32_t& r0, uint32_t& r1,
                                      uint32_t& r2, uint32_t& r3, uint32_t addr) {
    asm volatile("ldmatrix.sync.aligned.m8n8.x4.shared.b16 {%0,%1,%2,%3}, [%4];"
                 : "=r"(r0), "=r"(r1), "=r"(r2), "=r"(r3) : "r"(addr));
}

__device__ __forceinline__ uint32_t pack_f16x2(float lo, float hi) {
    uint32_t u;
    asm("cvt.rn.f16x2.f32 %0, %1, %2;" : "=r"(u) : "f"(hi), "f"(lo));
    return u;
}

__device__ __forceinline__ float ex2f(float x) {
    float y;
    asm("ex2.approx.f32 %0, %1;" : "=f"(y) : "f"(x));
    return y;
}

// ---------------------------------------------------------------------------
// Fused pre-pass (single launch):
//   blocks [0, XB)            : x fp32 -> fp16
//   blocks [XB, XB+WAB)       : W_attn [K,N] -> W_attn^T [N,K] fp16
//   blocks [XB+WAB, ...+WPB)  : W_proj  transpose
// ---------------------------------------------------------------------------
#define XB  (MROWS * EMB / 4 / 256)          // 6144
#define WAB ((EMB3 / 32) * (EMB / 32))       // 1728
#define WPB ((EMB / 32) * (EMB / 32))        // 576

__global__ void prepass_kernel(const float* __restrict__ x,
                               const float* __restrict__ Wa,
                               const float* __restrict__ Wp,
                               __half* __restrict__ x16,
                               __half* __restrict__ WaT,
                               __half* __restrict__ WpT)
{
    const int blk = blockIdx.x;
    const int tid = threadIdx.x;

    if (blk < XB) {
        const int i = blk * 256 + tid;
        float4 v = ((const float4*)x)[i];
        ((__half2*)x16)[2 * i]     = __floats2half2_rn(v.x, v.y);
        ((__half2*)x16)[2 * i + 1] = __floats2half2_rn(v.z, v.w);
        return;
    }

    __shared__ float t[32][33];
    const int tx = tid & 31;
    const int ty = tid >> 5;          // 0..7

    const float* W;
    __half* T;
    int N, idx;
    if (blk < XB + WAB) { W = Wa; T = WaT; N = EMB3; idx = blk - XB; }
    else                { W = Wp; T = WpT; N = EMB;  idx = blk - XB - WAB; }
    const int n0 = (idx % (N / 32)) * 32;
    const int k0 = (idx / (N / 32)) * 32;

#pragma unroll
    for (int i = 0; i < 4; i++)
        t[ty + i * 8][tx] = W[(size_t)(k0 + ty + i * 8) * N + n0 + tx];
    __syncthreads();
#pragma unroll
    for (int i = 0; i < 4; i++) {
        const int n = ty + i * 8;
        T[(size_t)(n0 + n) * EMB + k0 + tx] = __float2half_rn(t[tx][n]);
    }
}

// ---------------------------------------------------------------------------
// FP16 tensor-core GEMM (round-16 proven config): C = A @ B^T + bias.
// MT x 128 tile, BK=64, 256 thr, m16n8k16, ldmatrix, pitch 36 words.
// MODE 0: C fp32 [M,N]; MODE 1 (MT=128): QKV layout, Q pre-scaled by QSCALE.
// ---------------------------------------------------------------------------
#define GW 36   // smem pitch in 32-bit words (32 data + 4 pad)

template<int MODE, int MT>
__global__ __launch_bounds__(256)
void gemm_fp16_kernel(const __half* __restrict__ A, const __half* __restrict__ B,
                      const float* __restrict__ bias, float* __restrict__ C,
                      __half* __restrict__ QK, __half* __restrict__ VT,
                      int M, int N, int K)
{
    constexpr int MI = MT / 32;
    constexpr int AW = MT * GW;
    constexpr int SW = AW + 128 * GW;

    extern __shared__ uint32_t gsm[];

    const int tid    = threadIdx.x;
    const int lane   = tid & 31;
    const int warp   = tid >> 5;
    const int warp_m = warp >> 2;
    const int warp_n = warp & 3;
    const int gr     = lane >> 2;
    const int gc     = lane & 3;

    const int brow = blockIdx.y * MT;
    const int bcol = blockIdx.x * 128;

    const int lrow8 = lane & 7;
    const int segA  = (lane >> 3) & 1;
    const int segAc = lane >> 4;
    const int aLw = (segA * 8 + lrow8) * GW + segAc * 4;
    const int bLw = (segAc * 8 + lrow8) * GW + segA * 4;

    const uint32_t smb = (uint32_t)__cvta_generic_to_shared(gsm);

    float acc[MI][4][4];
#pragma unroll
    for (int i = 0; i < MI; i++)
#pragma unroll
        for (int j = 0; j < 4; j++)
#pragma unroll
            for (int v = 0; v < 4; v++) acc[i][j][v] = 0.f;

    const int NCH = K / 64;

    auto load_stage = [&](int s, int kc) {
        uint32_t* st = gsm + s * SW;
#pragma unroll
        for (int i = tid; i < MT * 8; i += 256) {
            const int r = i >> 3, u = i & 7;
            cpa16(st + r * GW + u * 4, A + (size_t)(brow + r) * K + kc + u * 8);
        }
#pragma unroll
        for (int i = tid; i < 128 * 8; i += 256) {
            const int r = i >> 3, u = i & 7;
            cpa16(st + AW + r * GW + u * 4, B + (size_t)(bcol + r) * K + kc + u * 8);
        }
    };

    load_stage(0, 0);
    cpa_commit();

    int buf = 0;
    for (int c = 0; c < NCH; c++) {
        cpa_wait<0>();
        __syncthreads();

        if (c + 1 < NCH) {
            load_stage(buf ^ 1, (c + 1) * 64);
            cpa_commit();
        }

        const uint32_t aBase = smb + (uint32_t)(buf * SW) * 4;
        const uint32_t bBase = smb + (uint32_t)(buf * SW + AW) * 4;

#pragma unroll
        for (int ks = 0; ks < 4; ks++) {
            const int w0 = ks * 8;
            uint32_t af[MI][4], bf[4][2];
#pragma unroll
            for (int mi = 0; mi < MI; mi++)
                ldsm4(af[mi][0], af[mi][1], af[mi][2], af[mi][3],
                      aBase + (uint32_t)(((warp_m * (MT / 2) + mi * 16) * GW + w0 + aLw) * 4));
#pragma unroll
            for (int p = 0; p < 2; p++)
                ldsm4(bf[2 * p][0], bf[2 * p][1], bf[2 * p + 1][0], bf[2 * p + 1][1],
                      bBase + (uint32_t)(((warp_n * 32 + p * 16) * GW + w0 + bLw) * 4));
#pragma unroll
            for (int mi = 0; mi < MI; mi++)
#pragma unroll
                for (int ni = 0; ni < 4; ni++)
                    mma_f16(acc[mi][ni][0], acc[mi][ni][1],
                            acc[mi][ni][2], acc[mi][ni][3],
                            af[mi][0], af[mi][1], af[mi][2], af[mi][3],
                            bf[ni][0], bf[ni][1]);
        }
        buf ^= 1;
    }

    // Epilogue
#pragma unroll
    for (int ni = 0; ni < 4; ni++) {
        const int col = bcol + warp_n * 32 + ni * 8 + 2 * gc;
        const float bv0 = bias[col];
        const float bv1 = bias[col + 1];
#pragma unroll
        for (int mi = 0; mi < MI; mi++) {
            const int row = brow + warp_m * (MT / 2) + mi * 16 + gr;
            float v00 = acc[mi][ni][0] + bv0, v01 = acc[mi][ni][1] + bv1;
            float v10 = acc[mi][ni][2] + bv0, v11 = acc[mi][ni][3] + bv1;
            if (MODE == 0) {
                *(float2*)&C[(size_t)row * N + col]       = make_float2(v00, v01);
                *(float2*)&C[(size_t)(row + 8) * N + col] = make_float2(v10, v11);
            } else {
                if (col < 1536) {
                    if (col < 768) {
                        v00 *= QSCALE; v01 *= QSCALE; v10 *= QSCALE; v11 *= QSCALE;
                    }
                    *(__half2*)&QK[(size_t)row * 1536 + col] = __floats2half2_rn(v00, v01);
                    *(__half2*)&QK[(size_t)(row + 8) * 1536 + col] = __floats2half2_rn(v10, v11);
                } else {
                    const int cc = col - 1536;
                    const int h  = cc >> 6;
                    const int d0 = cc & 63;
                    const int b  = row >> 10;
                    const int t  = row & 1023;
                    __half* base = VT + ((size_t)(b * NHEAD + h) * HDIM) * SEQ;
                    base[(size_t)d0 * SEQ + t]           = __float2half_rn(v00);
                    base[(size_t)(d0 + 1) * SEQ + t]     = __float2half_rn(v01);
                    base[(size_t)d0 * SEQ + t + 8]       = __float2half_rn(v10);
                    base[(size_t)(d0 + 1) * SEQ + t + 8] = __float2half_rn(v11);
                }
            }
        }
    }
}

#define G1_SMEM (2 * (128 + 128) * GW * 4)   // 73728 B
#define G2_SMEM (2 * (64 + 128) * GW * 4)    // 55296 B

// ---------------------------------------------------------------------------
// FP16 tensor-core flash attention.  128-key cp.async stages, ONE softmax
// per 128 keys (s[16][4] covers both 64-key sub-tiles), two PV passes
// sharing the P strip.  Log2-domain fp32 softmax.
// ---------------------------------------------------------------------------
#define APW 36
#define AT3_SMEM ((128 * APW + 4 * 64 * APW + 4 * 64 * APW) * 4)   // 92160 B

__global__ __launch_bounds__(256, 2)
void attn_f16_kernel(const __half* __restrict__ qk, const __half* __restrict__ vt,
                     __half* __restrict__ out16)
{
    extern __shared__ uint32_t smw[];
    uint32_t* QP  = smw;                   // 128 x APW : Q tile, later P strips
    uint32_t* Ks0 = QP + 128 * APW;        // 4 x 64 x APW (key sub-tiles)
    uint32_t* Vt0 = Ks0 + 4 * 64 * APW;    // 4 x 64 x APW (V^T sub-tiles)

    const int tid  = threadIdx.x;
    const int lane = tid & 31;
    const int warp = tid >> 5;
    const int gr   = lane >> 2;
    const int gc   = lane & 3;

    const int bh = blockIdx.y;
    const int b  = bh / NHEAD;
    const int h  = bh % NHEAD;
    const int qt = 7 - blockIdx.x;
    const int qbase = qt * 128;
    const int nst = qt + 1;                // 128-key stages

    const int lrow8 = lane & 7;
    const int segA  = (lane >> 3) & 1;
    const int segAc = lane >> 4;
    const int aLw = (segA * 8 + lrow8) * APW + segAc * 4;
    const int bLw = (segAc * 8 + lrow8) * APW + segA * 4;

    const uint32_t qpb = (uint32_t)__cvta_generic_to_shared(QP);
    const uint32_t ksb = (uint32_t)__cvta_generic_to_shared(Ks0);
    const uint32_t vtb = (uint32_t)__cvta_generic_to_shared(Vt0);

    const __half* kcol = qk + (size_t)b * SEQ * 1536 + 768 + h * HDIM;
    const __half* vrow = vt + (size_t)(b * NHEAD + h) * HDIM * SEQ;

    auto load_stage = [&](int s2, int kc) {
#pragma unroll
        for (int i = tid; i < 128 * 8; i += 256) {
            const int r = i >> 3, u = i & 7;
            cpa16(Ks0 + (s2 + (r >> 6)) * 64 * APW + (r & 63) * APW + u * 4,
                  kcol + (size_t)(kc + r) * 1536 + u * 8);
        }
#pragma unroll
        for (int i = tid; i < 64 * 16; i += 256) {
            const int d = i >> 4, u = i & 15;
            cpa16(Vt0 + (s2 + (u >> 3)) * 64 * APW + d * APW + (u & 7) * 4,
                  vrow + (size_t)d * SEQ + kc + (u >> 3) * 64 + (u & 7) * 8);
        }
    };

    // Q tile load
    {
        const int r = tid >> 1;
        const int u = (tid & 1) * 4;
        const __half* src = qk + (size_t)(b * SEQ + qbase + r) * 1536 + h * HDIM + u * 8;
        uint32_t* dst = QP + r * APW + u * 4;
#pragma unroll
        for (int i = 0; i < 4; i++)
            cpa16(dst + 4 * i, src + 8 * i);
    }
    load_stage(0, 0);
    cpa_commit();
    cpa_wait<0>();
    __syncthreads();

    uint32_t qf[4][4];
#pragma unroll
    for (int c = 0; c < 4; c++)
        ldsm4(qf[c][0], qf[c][1], qf[c][2], qf[c][3],
              qpb + (uint32_t)(((warp * 16) * APW + c * 8 + aLw) * 4));

    float o[8][4];
#pragma unroll
    for (int i = 0; i < 8; i++)
#pragma unroll
        for (int j = 0; j < 4; j++) o[i][j] = 0.f;
    float mr0 = -1e30f, mr1 = -1e30f, l0 = 0.f, l1 = 0.f;

    const int lrow = warp * 16 + gr;
    const int grow0 = qbase + lrow;
    const int strip_end = qbase + warp * 16 + 15;
    const int prow0 = lrow * APW;
    const int prow1 = (lrow + 8) * APW;

    int buf = 0;
    for (int st = 0; st < nst; st++) {
        cpa_wait<0>();
        __syncthreads();

        if (st + 1 < nst) {
            load_stage((buf ^ 1) * 2, (st + 1) * 128);
            cpa_commit();
        }

        const int kb0 = st * 128;
        const int kb1 = kb0 + 64;
        if (kb0 > strip_end) { buf ^= 1; continue; }
        const bool have1 = (kb1 <= strip_end);

        // ---- S' = Qs @ K^T for both sub-tiles (log2 domain) ----
        float s[16][4];
#pragma unroll
        for (int i = 0; i < 16; i++)
#pragma unroll
            for (int j = 0; j < 4; j++) s[i][j] = (i < 8) ? 0.f : -1e30f;

        {
            const uint32_t kBase = ksb + (uint32_t)(buf * 2) * (64 * APW * 4);
#pragma unroll
            for (int c = 0; c < 4; c++) {
                const int w0 = c * 8;
                uint32_t bf[8][2];
#pragma unroll
                for (int p = 0; p < 4; p++)
                    ldsm4(bf[2 * p][0], bf[2 * p][1], bf[2 * p + 1][0], bf[2 * p + 1][1],
                          kBase + (uint32_t)(((p * 16) * APW + w0 + bLw) * 4));
#pragma unroll
                for (int nt = 0; nt < 8; nt++)
                    mma_f16(s[nt][0], s[nt][1], s[nt][2], s[nt][3],
                            qf[c][0], qf[c][1], qf[c][2], qf[c][3],
                            bf[nt][0], bf[nt][1]);
            }
        }
        if (have1) {
#pragma unroll
            for (int i = 8; i < 16; i++)
#pragma unroll
                for (int j = 0; j < 4; j++) s[i][j] = 0.f;
            const uint32_t kBase = ksb + (uint32_t)(buf * 2 + 1) * (64 * APW * 4);
#pragma unroll
            for (int c = 0; c < 4; c++) {
                const int w0 = c * 8;
                uint32_t bf[8][2];
#pragma unroll
                for (int p = 0; p < 4; p++)
                    ldsm4(bf[2 * p][0], bf[2 * p][1], bf[2 * p + 1][0], bf[2 * p + 1][1],
                          kBase + (uint32_t)(((p * 16) * APW + w0 + bLw) * 4));
#pragma unroll
                for (int nt = 0; nt < 8; nt++)
                    mma_f16(s[8 + nt][0], s[8 + nt][1], s[8 + nt][2], s[8 + nt][3],
                            qf[c][0], qf[c][1], qf[c][2], qf[c][3],
                            bf[nt][0], bf[nt][1]);
            }
        }

        // ---- causal mask (both halves, global frame) ----
        if (kb0 + 63 > grow0) {
            const int lr0 = grow0, lr1 = grow0 + 8;
#pragma unroll
            for (int nt = 0; nt < 8; nt++) {
                const int c0 = kb0 + nt * 8 + 2 * gc;
                if (c0     > lr0) s[nt][0] = -1e30f;
                if (c0 + 1 > lr0) s[nt][1] = -1e30f;
                if (c0     > lr1) s[nt][2] = -1e30f;
                if (c0 + 1 > lr1) s[nt][3] = -1e30f;
            }
        }
        if (have1 && kb1 + 63 > grow0) {
            const int lr0 = grow0, lr1 = grow0 + 8;
#pragma unroll
            for (int nt = 0; nt < 8; nt++) {
                const int c0 = kb1 + nt * 8 + 2 * gc;
                if (c0     > lr0) s[8 + nt][0] = -1e30f;
                if (c0 + 1 > lr0) s[8 + nt][1] = -1e30f;
                if (c0     > lr1) s[8 + nt][2] = -1e30f;
                if (c0 + 1 > lr1) s[8 + nt][3] = -1e30f;
            }
        }

        // ---- ONE online softmax over 128 keys (log2 domain, fp32) ----
        float mx0 = -1e30f, mx1 = -1e30f;
#pragma unroll
        for (int nt = 0; nt < 16; nt++) {
            mx0 = fmaxf(mx0, fmaxf(s[nt][0], s[nt][1]));
            mx1 = fmaxf(mx1, fmaxf(s[nt][2], s[nt][3]));
        }
        mx0 = fmaxf(mx0, __shfl_xor_sync(0xffffffffu, mx0, 1));
        mx0 = fmaxf(mx0, __shfl_xor_sync(0xffffffffu, mx0, 2));
        mx1 = fmaxf(mx1, __shfl_xor_sync(0xffffffffu, mx1, 1));
        mx1 = fmaxf(mx1, __shfl_xor_sync(0xffffffffu, mx1, 2));

        const float mn0 = fmaxf(mr0, mx0);
        const float mn1 = fmaxf(mr1, mx1);
        const float a0  = ex2f(mr0 - mn0);
        const float a1  = ex2f(mr1 - mn1);
        mr0 = mn0; mr1 = mn1;

        float sum0 = 0.f, sum1 = 0.f;
#pragma unroll
        for (int nt = 0; nt < 16; nt++) {
            s[nt][0] = ex2f(s[nt][0] - mn0);
            s[nt][1] = ex2f(s[nt][1] - mn0);
            s[nt][2] = ex2f(s[nt][2] - mn1);
            s[nt][3] = ex2f(s[nt][3] - mn1);
            sum0 += s[nt][0] + s[nt][1];
            sum1 += s[nt][2] + s[nt][3];
        }
        sum0 += __shfl_xor_sync(0xffffffffu, sum0, 1);
        sum0 += __shfl_xor_sync(0xffffffffu, sum0, 2);
        sum1 += __shfl_xor_sync(0xffffffffu, sum1, 1);
        sum1 += __shfl_xor_sync(0xffffffffu, sum1, 2);
        l0 = l0 * a0 + sum0;
        l1 = l1 * a1 + sum1;

#pragma unroll
        for (int nt = 0; nt < 8; nt++) {
            o[nt][0] *= a0; o[nt][1] *= a0;
            o[nt][2] *= a1; o[nt][3] *= a1;
        }

        // ---- PV pass 0: P0 -> strip, O += P0 @ V0 ----
#pragma unroll
        for (int nt = 0; nt < 8; nt++) {
            QP[prow0 + nt * 4 + gc] = pack_f16x2(s[nt][0], s[nt][1]);
            QP[prow1 + nt * 4 + gc] = pack_f16x2(s[nt][2], s[nt][3]);
        }
        __syncwarp();
        {
            const uint32_t vBase = vtb + (uint32_t)(buf * 2) * (64 * APW * 4);
#pragma unroll
            for (int c = 0; c < 4; c++) {
                const int w0 = c * 8;
                uint32_t af[4];
                ldsm4(af[0], af[1], af[2], af[3],
                      qpb + (uint32_t)(((warp * 16) * APW + w0 + aLw) * 4));
                uint32_t bf[8][2];
#pragma unroll
                for (int p = 0; p < 4; p++)
                    ldsm4(bf[2 * p][0], bf[2 * p][1], bf[2 * p + 1][0], bf[2 * p + 1][1],
                          vBase + (uint32_t)(((p * 16) * APW + w0 + bLw) * 4));
#pragma unroll
                for (int nt = 0; nt < 8; nt++)
                    mma_f16(o[nt][0], o[nt][1], o[nt][2], o[nt][3],
                            af[0], af[1], af[2], af[3],
                            bf[nt][0], bf[nt][1]);
            }
        }
        __syncwarp();

        // ---- PV pass 1 (if second half live) ----
        if (have1) {
#pragma unroll
            for (int nt = 0; nt < 8; nt++) {
                QP[prow0 + nt * 4 + gc] = pack_f16x2(s[8 + nt][0], s[8 + nt][1]);
                QP[prow1 + nt * 4 + gc] = pack_f16x2(s[8 + nt][2], s[8 + nt][3]);
            }
            __syncwarp();
            const uint32_t vBase = vtb + (uint32_t)(buf * 2 + 1) * (64 * APW * 4);
#pragma unroll
            for (int c = 0; c < 4; c++) {
                const int w0 = c * 8;
                uint32_t af[4];
                ldsm4(af[0], af[1], af[2], af[3],
                      qpb + (uint32_t)(((warp * 16) * APW + w0 + aLw) * 4));
                uint32_t bf[8][2];
#pragma unroll
                for (int p = 0; p < 4; p++)
                    ldsm4(bf[2 * p][0], bf[2 * p][1], bf[2 * p + 1][0], bf[2 * p + 1][1],
                          vBase + (uint32_t)(((p * 16) * APW + w0 + bLw) * 4));
#pragma unroll
                for (int nt = 0; nt < 8; nt++)
                    mma_f16(o[nt][0], o[nt][1], o[nt][2], o[nt][3],
                            af[0], af[1], af[2], af[3],
                            bf[nt][0], bf[nt][1]);
            }
            __syncwarp();
        }
        buf ^= 1;
    }

    // ---- epilogue ----
    const float inv0 = 1.f / l0;
    const float inv1 = 1.f / l1;
    const int r0g = b * SEQ + grow0;
#pragma unroll
    for (int nt = 0; nt < 8; nt++) {
        const int col = h * HDIM + nt * 8 + 2 * gc;
        *(__half2*)&out16[(size_t)r0g * EMB + col] =
            __floats2half2_rn(o[nt][0] * inv0, o[nt][1] * inv0);
        *(__half2*)&out16[(size_t)(r0g + 8) * EMB + col] =
            __floats2half2_rn(o[nt][2] * inv1, o[nt][3] * inv1);
    }
}

// ---------------------------------------------------------------------------
extern "C" void kernel_launch(void* const* d_in, const int* in_sizes, int n_in,
                              void* d_out, int out_size)
{
    const float* x      = (const float*)d_in[0];
    const float* W_attn = (const float*)d_in[1];
    const float* b_attn = (const float*)d_in[2];
    const float* W_proj = (const float*)d_in[3];
    const float* b_proj = (const float*)d_in[4];
    float* out = (float*)d_out;

    __half *x16, *wat16, *wpt16, *qk16, *vt16, *at16;
    cudaGetSymbolAddress((void**)&x16,   g_x16);
    cudaGetSymbolAddress((void**)&wat16, g_wat16);
    cudaGetSymbolAddress((void**)&wpt16, g_wpt16);
    cudaGetSymbolAddress((void**)&qk16,  g_qk16);
    cudaGetSymbolAddress((void**)&vt16,  g_vt16);
    cudaGetSymbolAddress((void**)&at16,  g_at16);

    cudaFuncSetAttribute(attn_f16_kernel,
                         cudaFuncAttributeMaxDynamicSharedMemorySize, AT3_SMEM);
    cudaFuncSetAttribute(gemm_fp16_kernel<1, 128>,
                         cudaFuncAttributeMaxDynamicSharedMemorySize, G1_SMEM);
    cudaFuncSetAttribute(gemm_fp16_kernel<0, 64>,
                         cudaFuncAttributeMaxDynamicSharedMemorySize, G2_SMEM);

    const int M = MROWS;  // 8192

    // 0) fused pre-pass: x -> fp16, weights -> [N,K] fp16 (one launch)
    prepass_kernel<<<XB + WAB + WPB, 256>>>(x, W_attn, W_proj, x16, wat16, wpt16);

    // 1) QKV GEMM (fp16 mma, BK=64) -> Qs|K fp16 + V^T fp16
    gemm_fp16_kernel<1, 128><<<dim3(EMB3 / 128, M / 128), 256, G1_SMEM>>>(
        x16, wat16, b_attn, nullptr, qk16, vt16, M, EMB3, EMB);

    // 2) causal MHA (fp16 mma, 128-key stages, one softmax/stage) -> fp16
    attn_f16_kernel<<<dim3(SEQ / 128, BATCH * NHEAD), 256, AT3_SMEM>>>(
        qk16, vt16, at16);

    // 3) out = att @ W_proj + b_proj  (fp16 mma, BK=64, 64-row tiles)
    gemm_fp16_kernel<0, 64><<<dim3(EMB / 128, M / 64), 256, G2_SMEM>>>(
        at16, wpt16, b_proj, out, nullptr, nullptr, M, EMB, EMB);
}